// round 6
// baseline (speedup 1.0000x reference)
#include <cuda_runtime.h>
#include <cstdint>

// Problem constants (fixed by the reference)
#define T_DIM 1024
#define B_DIM 256
#define I_DIM 256
#define H_DIM 256
#define M_DIM (T_DIM * B_DIM)

// Scratch for X = inputs @ W_xh + b_h  (fp32, 268 MB)
__device__ float g_X[(size_t)M_DIM * H_DIM];

// ---------------------------------------------------------------------------
// packed f32x2 helpers
// ---------------------------------------------------------------------------
__device__ __forceinline__ void ffma2(unsigned long long& d,
                                      unsigned long long a,
                                      unsigned long long b) {
    asm("fma.rn.f32x2 %0, %1, %2, %0;" : "+l"(d) : "l"(a), "l"(b));
}
__device__ __forceinline__ unsigned long long pk2(float lo, float hi) {
    unsigned long long d;
    asm("mov.b64 %0, {%1, %2};" : "=l"(d) : "f"(lo), "f"(hi));
    return d;
}
__device__ __forceinline__ float2 upk2(unsigned long long a) {
    float2 v;
    asm("mov.b64 {%0, %1}, %2;" : "=f"(v.x), "=f"(v.y) : "l"(a));
    return v;
}
__device__ __forceinline__ float hsum2(unsigned long long a) {
    float2 v = upk2(a);
    return v.x + v.y;
}
// bf16x2 (lo=even k, hi=odd k) -> f32x2 (lo, hi)
__device__ __forceinline__ unsigned long long bf2f2(uint32_t b) {
    uint32_t lo = b << 16;
    uint32_t hi = b & 0xffff0000u;
    unsigned long long d;
    asm("mov.b64 %0, {%1, %2};" : "=l"(d) : "r"(lo), "r"(hi));
    return d;
}
// pack two fp32 -> bf16x2 with lo=a, hi=b
__device__ __forceinline__ uint32_t f2bf2(float lo, float hi) {
    uint32_t d;
    asm("cvt.rn.bf16x2.f32 %0, %1, %2;" : "=r"(d) : "f"(hi), "f"(lo));
    return d;
}
// fast, accurate tanh: (e^{2x}-1) * rcp(e^{2x}+1)
__device__ __forceinline__ float fast_tanh(float x) {
    float e, r;
    asm("ex2.approx.f32 %0, %1;" : "=f"(e) : "f"(x * 2.8853900817779268f));
    asm("rcp.approx.f32 %0, %1;" : "=f"(r) : "f"(e + 1.0f));
    return (e - 1.0f) * r;
}

// ---------------------------------------------------------------------------
// Kernel 1: X = inputs @ W_xh + b_h  (fp32 SGEMM, f32x2 accumulation,
// B tile stored PRE-DUPLICATED as (b,b) u64 pairs -> no per-iter packing movs)
// ---------------------------------------------------------------------------
#define BM 128
#define BN 128
#define BK 8
#define TM 8
#define TN 8

__global__ __launch_bounds__(256) void gemm_xh_kernel(
    const float* __restrict__ A,
    const float* __restrict__ Bw,
    const float* __restrict__ bias)
{
    __shared__ float As[BK * BM];                       // transposed A tile
    __shared__ unsigned long long Bs2[BK * BN];         // duplicated (b,b)

    const int mTile = blockIdx.x;
    const int nTile = blockIdx.y;
    const int tid = threadIdx.x;

    const int tx = tid % (BN / TN);
    const int ty = tid / (BN / TN);

    const int aRow = tid >> 1;
    const int aCol = (tid & 1) * 4;
    const int bRow = tid >> 5;
    const int bCol = (tid & 31) * 4;

    const float* Ag = A + (size_t)mTile * BM * I_DIM;
    const float* Bg = Bw + nTile * BN;

    unsigned long long acc2[4][TN];
#pragma unroll
    for (int i = 0; i < 4; i++)
#pragma unroll
        for (int j = 0; j < TN; j++) acc2[i][j] = 0ull;

    for (int k0 = 0; k0 < I_DIM; k0 += BK) {
        float4 a = *(const float4*)&Ag[(size_t)aRow * I_DIM + k0 + aCol];
        As[(aCol + 0) * BM + aRow] = a.x;
        As[(aCol + 1) * BM + aRow] = a.y;
        As[(aCol + 2) * BM + aRow] = a.z;
        As[(aCol + 3) * BM + aRow] = a.w;
        float4 b = *(const float4*)&Bg[(size_t)(k0 + bRow) * H_DIM + bCol];
        unsigned long long* bp = &Bs2[bRow * BN + bCol];
        bp[0] = pk2(b.x, b.x);
        bp[1] = pk2(b.y, b.y);
        bp[2] = pk2(b.z, b.z);
        bp[3] = pk2(b.w, b.w);
        __syncthreads();

#pragma unroll
        for (int k = 0; k < BK; k++) {
            ulonglong2 am0 = *(const ulonglong2*)&As[k * BM + ty * TM + 0];
            ulonglong2 am1 = *(const ulonglong2*)&As[k * BM + ty * TM + 4];
            unsigned long long ap[4] = {am0.x, am0.y, am1.x, am1.y};
            const ulonglong2* bq = (const ulonglong2*)&Bs2[k * BN + tx * TN];
            ulonglong2 b01 = bq[0], b23 = bq[1], b45 = bq[2], b67 = bq[3];
            unsigned long long bd[TN] = {b01.x, b01.y, b23.x, b23.y,
                                         b45.x, b45.y, b67.x, b67.y};
#pragma unroll
            for (int i = 0; i < 4; i++)
#pragma unroll
                for (int j = 0; j < TN; j++)
                    ffma2(acc2[i][j], ap[i], bd[j]);
        }
        __syncthreads();
    }

    const int nBase = nTile * BN + tx * TN;
    float bv[TN];
#pragma unroll
    for (int j = 0; j < TN; j++) bv[j] = bias[nBase + j];

#pragma unroll
    for (int i = 0; i < 4; i++) {
        size_t row0 = (size_t)mTile * BM + ty * TM + 2 * i;
        float r0[TN], r1[TN];
#pragma unroll
        for (int j = 0; j < TN; j++) {
            float2 v = upk2(acc2[i][j]);
            r0[j] = v.x + bv[j];
            r1[j] = v.y + bv[j];
        }
        *(float4*)&g_X[row0 * H_DIM + nBase + 0] = make_float4(r0[0], r0[1], r0[2], r0[3]);
        *(float4*)&g_X[row0 * H_DIM + nBase + 4] = make_float4(r0[4], r0[5], r0[6], r0[7]);
        *(float4*)&g_X[(row0 + 1) * H_DIM + nBase + 0] = make_float4(r1[0], r1[1], r1[2], r1[3]);
        *(float4*)&g_X[(row0 + 1) * H_DIM + nBase + 4] = make_float4(r1[4], r1[5], r1[6], r1[7]);
    }
}

// ---------------------------------------------------------------------------
// Kernel 2: the recurrence.
// 128 CTAs x 512 threads; thread = (column-pair p 0..127, k-split s 0..3).
// Weights: k in [64s, 64s+32) in fp32 registers (exact),
//          k in [64s+32, 64s+64) in smem as bf16x2 (half the LDS bytes),
//          decompressed inline with shift/mask to f32x2.
// Double-buffered skewed state, one barrier/step, reduce-scatter epilogue.
// ---------------------------------------------------------------------------
#define SROW 272                               // skewed state row stride (floats)
#define BUF_F (2 * SROW)
// bf16 weight block per (s,p): 8 uint4 data + 1 uint4 pad = 36 u32
#define PAIR_STRIDE_U32 36
#define SPLIT_STRIDE_U32 (128 * PAIR_STRIDE_U32 + 4)
#define SMEM_STATE_F (2 * BUF_F)
#define RNN_SMEM_F (SMEM_STATE_F + 4 * SPLIT_STRIDE_U32)
#define RNN_SMEM_B (RNN_SMEM_F * 4)

__global__ __launch_bounds__(512, 1) void rnn_kernel(
    const float* __restrict__ W,      // W_hh [k][h]
    float* __restrict__ out,          // outputs [T,B,H] (+ optional state [B,H])
    int write_state)
{
    extern __shared__ float sm[];
    float* S0 = sm;
    float* S1 = sm + BUF_F;
    uint32_t* WB = (uint32_t*)(sm + SMEM_STATE_F);   // bf16 packed weights

    const int tid = threadIdx.x;
    const int wid = tid >> 5;
    const int lane = tid & 31;
    const int p = wid * 8 + (lane & 7);
    const int s = lane >> 3;
    const int h0 = 2 * p;
    const int kbase = 64 * s;
    const int bidx0 = blockIdx.x * 2;
    const int hs = h0 + ((h0 >> 6) << 2);
    const bool sb0 = (s & 1);
    const int sb1 = (s >> 1);

    // register-resident fp32 weights: k in [kbase, kbase+32), packed (k, k+1)
    unsigned long long wrA[16], wrB[16];
#pragma unroll
    for (int j = 0; j < 16; j++) {
        int k = kbase + 2 * j;
        float2 wk  = *(const float2*)&W[(size_t)k * H_DIM + h0];
        float2 wk1 = *(const float2*)&W[(size_t)(k + 1) * H_DIM + h0];
        wrA[j] = pk2(wk.x, wk1.x);
        wrB[j] = pk2(wk.y, wk1.y);
    }

    // smem-resident bf16 weights: k in [kbase+32, kbase+64)
    // layout per (s,p): u32[2j] = colA pair j (even k lo, odd k hi), u32[2j+1] = colB pair j
    uint32_t* myWB = WB + s * SPLIT_STRIDE_U32 + p * PAIR_STRIDE_U32;
#pragma unroll
    for (int j = 0; j < 16; j++) {
        int k = kbase + 32 + 2 * j;
        float2 wk  = *(const float2*)&W[(size_t)k * H_DIM + h0];
        float2 wk1 = *(const float2*)&W[(size_t)(k + 1) * H_DIM + h0];
        myWB[2 * j]     = f2bf2(wk.x, wk1.x);
        myWB[2 * j + 1] = f2bf2(wk.y, wk1.y);
    }

    // zero both state buffers (incl. pads)
    for (int i = tid; i < SMEM_STATE_F; i += 512) sm[i] = 0.0f;
    __syncthreads();

    const uint4* wq = (const uint4*)myWB;    // 8 entries of 4 bf16x2 pairs
    const int stoff = sb1 * SROW + hs + (sb0 ? 1 : 0);
    const size_t goff = (size_t)(bidx0 + sb1) * H_DIM + h0 + (sb0 ? 1 : 0);
    float* outp = out + goff;
    const float* xp = g_X + goff;
    float* state_out = out + (size_t)T_DIM * B_DIM * H_DIM + goff;

    float x_nxt = *xp;   // x(t=0)

    auto step = [&](int t, const float* Sr, float* Sw) {
        const ulonglong2* su0 = (const ulonglong2*)(Sr + 68 * s);
        const ulonglong2* su1 = (const ulonglong2*)(Sr + SROW + 68 * s);

        float x_cur = x_nxt;
        int tn = (t + 1 < T_DIM) ? (t + 1) : t;
        x_nxt = xp[(size_t)tn * (B_DIM * H_DIM)];

        unsigned long long a00 = 0ull, a01 = 0ull, a10 = 0ull, a11 = 0ull;

        // fp32 register half: k offsets [0,32)
#pragma unroll
        for (int j2 = 0; j2 < 8; j2++) {
            ulonglong2 s0 = su0[j2];
            ulonglong2 s1 = su1[j2];
            ffma2(a00, s0.x, wrA[2 * j2]);     ffma2(a01, s0.x, wrB[2 * j2]);
            ffma2(a00, s0.y, wrA[2 * j2 + 1]); ffma2(a01, s0.y, wrB[2 * j2 + 1]);
            ffma2(a10, s1.x, wrA[2 * j2]);     ffma2(a11, s1.x, wrB[2 * j2]);
            ffma2(a10, s1.y, wrA[2 * j2 + 1]); ffma2(a11, s1.y, wrB[2 * j2 + 1]);
        }
        // bf16 smem half: k offsets [32,64)
#pragma unroll
        for (int j2 = 0; j2 < 8; j2++) {
            uint4 q = wq[j2];
            unsigned long long wA0 = bf2f2(q.x);
            unsigned long long wB0 = bf2f2(q.y);
            unsigned long long wA1 = bf2f2(q.z);
            unsigned long long wB1 = bf2f2(q.w);
            ulonglong2 s0 = su0[8 + j2];
            ulonglong2 s1 = su1[8 + j2];
            ffma2(a00, s0.x, wA0); ffma2(a01, s0.x, wB0);
            ffma2(a00, s0.y, wA1); ffma2(a01, s0.y, wB1);
            ffma2(a10, s1.x, wA0); ffma2(a11, s1.x, wB0);
            ffma2(a10, s1.y, wA1); ffma2(a11, s1.y, wB1);
        }

        float f00 = hsum2(a00), f01 = hsum2(a01);
        float f10 = hsum2(a10), f11 = hsum2(a11);

        // 2-level reduce-scatter over the 4 k-splits (3 scalar SHFLs)
        float m0 = sb0 ? f01 : f00;
        float m1 = sb0 ? f11 : f10;
        float o0 = sb0 ? f00 : f01;
        float o1 = sb0 ? f10 : f11;
        m0 += __shfl_xor_sync(0xffffffffu, o0, 8);
        m1 += __shfl_xor_sync(0xffffffffu, o1, 8);
        float mm = sb1 ? m1 : m0;
        float oo = sb1 ? m0 : m1;
        mm += __shfl_xor_sync(0xffffffffu, oo, 16);

        float h = fast_tanh(mm + x_cur);

        Sw[stoff] = h;
        outp[(size_t)t * (B_DIM * H_DIM)] = h;

        __syncthreads();
    };

#pragma unroll 1
    for (int t = 0; t < T_DIM; t += 2) {
        step(t,     S0, S1);
        step(t + 1, S1, S0);
    }

    // final state (last write went to S0; guarded by the loop's trailing barrier)
    if (write_state) *state_out = S0[stoff];
}

// ---------------------------------------------------------------------------
// Launch
// ---------------------------------------------------------------------------
extern "C" void kernel_launch(void* const* d_in, const int* in_sizes, int n_in,
                              void* d_out, int out_size)
{
    (void)n_in; (void)in_sizes;
    const float* inputs = (const float*)d_in[0];  // [T,B,I]
    const float* W_xh   = (const float*)d_in[1];  // [I,H]
    const float* W_hh   = (const float*)d_in[2];  // [H,H]
    const float* b_h    = (const float*)d_in[3];  // [H]
    float* out = (float*)d_out;

    const long long need = (long long)T_DIM * B_DIM * H_DIM + (long long)B_DIM * H_DIM;
    int write_state = ((long long)out_size >= need) ? 1 : 0;

    dim3 g1(M_DIM / BM, H_DIM / BN);
    gemm_xh_kernel<<<g1, 256>>>(inputs, W_xh, b_h);

    cudaFuncSetAttribute(rnn_kernel, cudaFuncAttributeMaxDynamicSharedMemorySize,
                         RNN_SMEM_B);
    rnn_kernel<<<B_DIM / 2, 512, RNN_SMEM_B>>>(W_hh, out, write_state);
}

// round 7
// speedup vs baseline: 1.7633x; 1.7633x over previous
#include <cuda_runtime.h>
#include <cstdint>

// Problem constants (fixed by the reference)
#define T_DIM 1024
#define B_DIM 256
#define I_DIM 256
#define H_DIM 256
#define M_DIM (T_DIM * B_DIM)

// Scratch for X = inputs @ W_xh + b_h  (fp32, 268 MB)
__device__ float g_X[(size_t)M_DIM * H_DIM];

// ---------------------------------------------------------------------------
// packed f32x2 helpers
// ---------------------------------------------------------------------------
__device__ __forceinline__ void ffma2(unsigned long long& d,
                                      unsigned long long a,
                                      unsigned long long b) {
    asm("fma.rn.f32x2 %0, %1, %2, %0;" : "+l"(d) : "l"(a), "l"(b));
}
__device__ __forceinline__ unsigned long long pk2(float lo, float hi) {
    unsigned long long d;
    asm("mov.b64 %0, {%1, %2};" : "=l"(d) : "f"(lo), "f"(hi));
    return d;
}
__device__ __forceinline__ float2 upk2(unsigned long long a) {
    float2 v;
    asm("mov.b64 {%0, %1}, %2;" : "=f"(v.x), "=f"(v.y) : "l"(a));
    return v;
}
__device__ __forceinline__ float hsum2(unsigned long long a) {
    float2 v = upk2(a);
    return v.x + v.y;
}
// bf16x2 (lo=even k, hi=odd k) -> f32x2 (lo, hi)
__device__ __forceinline__ unsigned long long bf2f2(uint32_t b) {
    uint32_t lo = b << 16;
    uint32_t hi = b & 0xffff0000u;
    unsigned long long d;
    asm("mov.b64 %0, {%1, %2};" : "=l"(d) : "r"(lo), "r"(hi));
    return d;
}
// pack two fp32 -> bf16x2 with lo=a, hi=b
__device__ __forceinline__ uint32_t f2bf2(float lo, float hi) {
    uint32_t d;
    asm("cvt.rn.bf16x2.f32 %0, %1, %2;" : "=r"(d) : "f"(hi), "f"(lo));
    return d;
}
// fast, accurate tanh: (e^{2x}-1) * rcp(e^{2x}+1)
__device__ __forceinline__ float fast_tanh(float x) {
    float e, r;
    asm("ex2.approx.f32 %0, %1;" : "=f"(e) : "f"(x * 2.8853900817779268f));
    asm("rcp.approx.f32 %0, %1;" : "=f"(r) : "f"(e + 1.0f));
    return (e - 1.0f) * r;
}

// ---------------------------------------------------------------------------
// Kernel 1: X = inputs @ W_xh + b_h  (fp32 SGEMM, f32x2 accumulation,
// round-5 inner loop + ping-pong smem double buffering: ONE barrier per
// k-tile, global loads for tile i+1 overlap compute of tile i)
// ---------------------------------------------------------------------------
#define BM 128
#define BN 128
#define BK 8
#define TM 8
#define TN 8
#define NKT (I_DIM / BK)   // 32 k-tiles

__global__ __launch_bounds__(256) void gemm_xh_kernel(
    const float* __restrict__ A,
    const float* __restrict__ Bw,
    const float* __restrict__ bias)
{
    __shared__ float As[2][BK * BM];
    __shared__ float Bs[2][BK * BN];

    const int mTile = blockIdx.x;
    const int nTile = blockIdx.y;
    const int tid = threadIdx.x;

    const int tx = tid % (BN / TN);
    const int ty = tid / (BN / TN);

    const int aRow = tid >> 1;
    const int aCol = (tid & 1) * 4;
    const int bRow = tid >> 5;
    const int bCol = (tid & 31) * 4;

    const float* Ag = A + (size_t)mTile * BM * I_DIM;
    const float* Bg = Bw + nTile * BN;

    unsigned long long acc2[4][TN];
#pragma unroll
    for (int i = 0; i < 4; i++)
#pragma unroll
        for (int j = 0; j < TN; j++) acc2[i][j] = 0ull;

    // preload tile 0
    {
        float4 a = *(const float4*)&Ag[(size_t)aRow * I_DIM + aCol];
        As[0][(aCol + 0) * BM + aRow] = a.x;
        As[0][(aCol + 1) * BM + aRow] = a.y;
        As[0][(aCol + 2) * BM + aRow] = a.z;
        As[0][(aCol + 3) * BM + aRow] = a.w;
        float4 b = *(const float4*)&Bg[(size_t)bRow * H_DIM + bCol];
        *(float4*)&Bs[0][bRow * BN + bCol] = b;
    }
    __syncthreads();

#pragma unroll 1
    for (int it = 0; it < NKT; it++) {
        const int cur = it & 1;
        // prefetch next tile global -> regs
        float4 an, bn;
        if (it + 1 < NKT) {
            int k0 = (it + 1) * BK;
            an = *(const float4*)&Ag[(size_t)aRow * I_DIM + k0 + aCol];
            bn = *(const float4*)&Bg[(size_t)(k0 + bRow) * H_DIM + bCol];
        }

#pragma unroll
        for (int k = 0; k < BK; k++) {
            ulonglong2 am0 = *(const ulonglong2*)&As[cur][k * BM + ty * TM + 0];
            ulonglong2 am1 = *(const ulonglong2*)&As[cur][k * BM + ty * TM + 4];
            unsigned long long ap[4] = {am0.x, am0.y, am1.x, am1.y};
            float4 n0 = *(const float4*)&Bs[cur][k * BN + tx * TN + 0];
            float4 n1 = *(const float4*)&Bs[cur][k * BN + tx * TN + 4];
            unsigned long long bd[TN];
            bd[0] = pk2(n0.x, n0.x); bd[1] = pk2(n0.y, n0.y);
            bd[2] = pk2(n0.z, n0.z); bd[3] = pk2(n0.w, n0.w);
            bd[4] = pk2(n1.x, n1.x); bd[5] = pk2(n1.y, n1.y);
            bd[6] = pk2(n1.z, n1.z); bd[7] = pk2(n1.w, n1.w);
#pragma unroll
            for (int i = 0; i < 4; i++)
#pragma unroll
                for (int j = 0; j < TN; j++)
                    ffma2(acc2[i][j], ap[i], bd[j]);
        }

        if (it + 1 < NKT) {
            const int nxt = cur ^ 1;
            As[nxt][(aCol + 0) * BM + aRow] = an.x;
            As[nxt][(aCol + 1) * BM + aRow] = an.y;
            As[nxt][(aCol + 2) * BM + aRow] = an.z;
            As[nxt][(aCol + 3) * BM + aRow] = an.w;
            *(float4*)&Bs[nxt][bRow * BN + bCol] = bn;
            __syncthreads();
        }
    }

    const int nBase = nTile * BN + tx * TN;
    float bv[TN];
#pragma unroll
    for (int j = 0; j < TN; j++) bv[j] = bias[nBase + j];

#pragma unroll
    for (int i = 0; i < 4; i++) {
        size_t row0 = (size_t)mTile * BM + ty * TM + 2 * i;
        float r0[TN], r1[TN];
#pragma unroll
        for (int j = 0; j < TN; j++) {
            float2 v = upk2(acc2[i][j]);
            r0[j] = v.x + bv[j];
            r1[j] = v.y + bv[j];
        }
        *(float4*)&g_X[row0 * H_DIM + nBase + 0] = make_float4(r0[0], r0[1], r0[2], r0[3]);
        *(float4*)&g_X[row0 * H_DIM + nBase + 4] = make_float4(r0[4], r0[5], r0[6], r0[7]);
        *(float4*)&g_X[(row0 + 1) * H_DIM + nBase + 0] = make_float4(r1[0], r1[1], r1[2], r1[3]);
        *(float4*)&g_X[(row0 + 1) * H_DIM + nBase + 4] = make_float4(r1[4], r1[5], r1[6], r1[7]);
    }
}

// ---------------------------------------------------------------------------
// Kernel 2: the recurrence (unchanged from round 6 — measured 1085us).
// 128 CTAs x 512 threads; thread = (column-pair p 0..127, k-split s 0..3).
// Weights: k in [64s, 64s+32) in fp32 registers (exact),
//          k in [64s+32, 64s+64) in smem as bf16x2.
// Double-buffered skewed state, one barrier/step, reduce-scatter epilogue.
// ---------------------------------------------------------------------------
#define SROW 272
#define BUF_F (2 * SROW)
#define PAIR_STRIDE_U32 36
#define SPLIT_STRIDE_U32 (128 * PAIR_STRIDE_U32 + 4)
#define SMEM_STATE_F (2 * BUF_F)
#define RNN_SMEM_F (SMEM_STATE_F + 4 * SPLIT_STRIDE_U32)
#define RNN_SMEM_B (RNN_SMEM_F * 4)

__global__ __launch_bounds__(512, 1) void rnn_kernel(
    const float* __restrict__ W,
    float* __restrict__ out,
    int write_state)
{
    extern __shared__ float sm[];
    float* S0 = sm;
    float* S1 = sm + BUF_F;
    uint32_t* WB = (uint32_t*)(sm + SMEM_STATE_F);

    const int tid = threadIdx.x;
    const int wid = tid >> 5;
    const int lane = tid & 31;
    const int p = wid * 8 + (lane & 7);
    const int s = lane >> 3;
    const int h0 = 2 * p;
    const int kbase = 64 * s;
    const int bidx0 = blockIdx.x * 2;
    const int hs = h0 + ((h0 >> 6) << 2);
    const bool sb0 = (s & 1);
    const int sb1 = (s >> 1);

    unsigned long long wrA[16], wrB[16];
#pragma unroll
    for (int j = 0; j < 16; j++) {
        int k = kbase + 2 * j;
        float2 wk  = *(const float2*)&W[(size_t)k * H_DIM + h0];
        float2 wk1 = *(const float2*)&W[(size_t)(k + 1) * H_DIM + h0];
        wrA[j] = pk2(wk.x, wk1.x);
        wrB[j] = pk2(wk.y, wk1.y);
    }

    uint32_t* myWB = WB + s * SPLIT_STRIDE_U32 + p * PAIR_STRIDE_U32;
#pragma unroll
    for (int j = 0; j < 16; j++) {
        int k = kbase + 32 + 2 * j;
        float2 wk  = *(const float2*)&W[(size_t)k * H_DIM + h0];
        float2 wk1 = *(const float2*)&W[(size_t)(k + 1) * H_DIM + h0];
        myWB[2 * j]     = f2bf2(wk.x, wk1.x);
        myWB[2 * j + 1] = f2bf2(wk.y, wk1.y);
    }

    for (int i = tid; i < SMEM_STATE_F; i += 512) sm[i] = 0.0f;
    __syncthreads();

    const uint4* wq = (const uint4*)myWB;
    const int stoff = sb1 * SROW + hs + (sb0 ? 1 : 0);
    const size_t goff = (size_t)(bidx0 + sb1) * H_DIM + h0 + (sb0 ? 1 : 0);
    float* outp = out + goff;
    const float* xp = g_X + goff;
    float* state_out = out + (size_t)T_DIM * B_DIM * H_DIM + goff;

    float x_nxt = *xp;

    auto step = [&](int t, const float* Sr, float* Sw) {
        const ulonglong2* su0 = (const ulonglong2*)(Sr + 68 * s);
        const ulonglong2* su1 = (const ulonglong2*)(Sr + SROW + 68 * s);

        float x_cur = x_nxt;
        int tn = (t + 1 < T_DIM) ? (t + 1) : t;
        x_nxt = xp[(size_t)tn * (B_DIM * H_DIM)];

        unsigned long long a00 = 0ull, a01 = 0ull, a10 = 0ull, a11 = 0ull;

#pragma unroll
        for (int j2 = 0; j2 < 8; j2++) {
            ulonglong2 s0 = su0[j2];
            ulonglong2 s1 = su1[j2];
            ffma2(a00, s0.x, wrA[2 * j2]);     ffma2(a01, s0.x, wrB[2 * j2]);
            ffma2(a00, s0.y, wrA[2 * j2 + 1]); ffma2(a01, s0.y, wrB[2 * j2 + 1]);
            ffma2(a10, s1.x, wrA[2 * j2]);     ffma2(a11, s1.x, wrB[2 * j2]);
            ffma2(a10, s1.y, wrA[2 * j2 + 1]); ffma2(a11, s1.y, wrB[2 * j2 + 1]);
        }
#pragma unroll
        for (int j2 = 0; j2 < 8; j2++) {
            uint4 q = wq[j2];
            unsigned long long wA0 = bf2f2(q.x);
            unsigned long long wB0 = bf2f2(q.y);
            unsigned long long wA1 = bf2f2(q.z);
            unsigned long long wB1 = bf2f2(q.w);
            ulonglong2 s0 = su0[8 + j2];
            ulonglong2 s1 = su1[8 + j2];
            ffma2(a00, s0.x, wA0); ffma2(a01, s0.x, wB0);
            ffma2(a00, s0.y, wA1); ffma2(a01, s0.y, wB1);
            ffma2(a10, s1.x, wA0); ffma2(a11, s1.x, wB0);
            ffma2(a10, s1.y, wA1); ffma2(a11, s1.y, wB1);
        }

        float f00 = hsum2(a00), f01 = hsum2(a01);
        float f10 = hsum2(a10), f11 = hsum2(a11);

        float m0 = sb0 ? f01 : f00;
        float m1 = sb0 ? f11 : f10;
        float o0 = sb0 ? f00 : f01;
        float o1 = sb0 ? f10 : f11;
        m0 += __shfl_xor_sync(0xffffffffu, o0, 8);
        m1 += __shfl_xor_sync(0xffffffffu, o1, 8);
        float mm = sb1 ? m1 : m0;
        float oo = sb1 ? m0 : m1;
        mm += __shfl_xor_sync(0xffffffffu, oo, 16);

        float h = fast_tanh(mm + x_cur);

        Sw[stoff] = h;
        outp[(size_t)t * (B_DIM * H_DIM)] = h;

        __syncthreads();
    };

#pragma unroll 1
    for (int t = 0; t < T_DIM; t += 2) {
        step(t,     S0, S1);
        step(t + 1, S1, S0);
    }

    if (write_state) *state_out = S0[stoff];
}

// ---------------------------------------------------------------------------
// Launch
// ---------------------------------------------------------------------------
extern "C" void kernel_launch(void* const* d_in, const int* in_sizes, int n_in,
                              void* d_out, int out_size)
{
    (void)n_in; (void)in_sizes;
    const float* inputs = (const float*)d_in[0];  // [T,B,I]
    const float* W_xh   = (const float*)d_in[1];  // [I,H]
    const float* W_hh   = (const float*)d_in[2];  // [H,H]
    const float* b_h    = (const float*)d_in[3];  // [H]
    float* out = (float*)d_out;

    const long long need = (long long)T_DIM * B_DIM * H_DIM + (long long)B_DIM * H_DIM;
    int write_state = ((long long)out_size >= need) ? 1 : 0;

    dim3 g1(M_DIM / BM, H_DIM / BN);
    gemm_xh_kernel<<<g1, 256>>>(inputs, W_xh, b_h);

    cudaFuncSetAttribute(rnn_kernel, cudaFuncAttributeMaxDynamicSharedMemorySize,
                         RNN_SMEM_B);
    rnn_kernel<<<B_DIM / 2, 512, RNN_SMEM_B>>>(W_hh, out, write_state);
}

// round 8
// speedup vs baseline: 1.8518x; 1.0502x over previous
#include <cuda_runtime.h>
#include <cstdint>

// Problem constants (fixed by the reference)
#define T_DIM 1024
#define B_DIM 256
#define I_DIM 256
#define H_DIM 256
#define M_DIM (T_DIM * B_DIM)

// Scratch for X = inputs @ W_xh + b_h  (fp32, 268 MB)
__device__ float g_X[(size_t)M_DIM * H_DIM];

// ---------------------------------------------------------------------------
// packed f32x2 helpers
// ---------------------------------------------------------------------------
__device__ __forceinline__ void ffma2(unsigned long long& d,
                                      unsigned long long a,
                                      unsigned long long b) {
    asm("fma.rn.f32x2 %0, %1, %2, %0;" : "+l"(d) : "l"(a), "l"(b));
}
__device__ __forceinline__ unsigned long long pk2(float lo, float hi) {
    unsigned long long d;
    asm("mov.b64 %0, {%1, %2};" : "=l"(d) : "f"(lo), "f"(hi));
    return d;
}
__device__ __forceinline__ float2 upk2(unsigned long long a) {
    float2 v;
    asm("mov.b64 {%0, %1}, %2;" : "=f"(v.x), "=f"(v.y) : "l"(a));
    return v;
}
__device__ __forceinline__ float hsum2(unsigned long long a) {
    float2 v = upk2(a);
    return v.x + v.y;
}
// bf16x2 (lo=even k, hi=odd k) -> f32x2 (lo, hi)
__device__ __forceinline__ unsigned long long bf2f2(uint32_t b) {
    uint32_t lo = b << 16;
    uint32_t hi = b & 0xffff0000u;
    unsigned long long d;
    asm("mov.b64 %0, {%1, %2};" : "=l"(d) : "r"(lo), "r"(hi));
    return d;
}
// pack two fp32 -> bf16x2 with lo=a, hi=b
__device__ __forceinline__ uint32_t f2bf2(float lo, float hi) {
    uint32_t d;
    asm("cvt.rn.bf16x2.f32 %0, %1, %2;" : "=r"(d) : "f"(hi), "f"(lo));
    return d;
}
// fast, accurate tanh: (e^{2x}-1) * rcp(e^{2x}+1)
__device__ __forceinline__ float fast_tanh(float x) {
    float e, r;
    asm("ex2.approx.f32 %0, %1;" : "=f"(e) : "f"(x * 2.8853900817779268f));
    asm("rcp.approx.f32 %0, %1;" : "=f"(r) : "f"(e + 1.0f));
    return (e - 1.0f) * r;
}

// ---------------------------------------------------------------------------
// Kernel 1: X = inputs @ W_xh + b_h  (fp32 SGEMM, f32x2 accumulation,
// ping-pong smem double buffering + BANK-PADDED Bs:
// a 16B pad after every 32 data floats (row stride 144) spreads each k-row's
// 16 read chunks over all 8 bank-quads (exactly 2x each) -> Bs reads hit the
// 2-wavefront byte floor instead of 4-way conflicts.
// float offset of data float f within a k-row: f + 4*(f>>5).
// ---------------------------------------------------------------------------
#define BM 128
#define BN 128
#define BK 8
#define TM 8
#define TN 8
#define NKT (I_DIM / BK)   // 32 k-tiles
#define BROW 144           // padded Bs row stride in floats

__global__ __launch_bounds__(256) void gemm_xh_kernel(
    const float* __restrict__ A,
    const float* __restrict__ Bw,
    const float* __restrict__ bias)
{
    __shared__ float As[2][BK * BM];
    __shared__ float Bs[2][BK * BROW];

    const int mTile = blockIdx.x;
    const int nTile = blockIdx.y;
    const int tid = threadIdx.x;

    const int tx = tid % (BN / TN);   // 0..15
    const int ty = tid / (BN / TN);   // 0..15

    const int aRow = tid >> 1;
    const int aCol = (tid & 1) * 4;
    const int bRow = tid >> 5;                       // 0..7
    const int bCol = (tid & 31) * 4;                 // 0..124 (data index)
    const int bColP = bCol + 4 * (bCol >> 5);        // padded store offset

    // padded read offsets for this thread's 8 columns (two adjacent float4)
    const int nRdP = 8 * tx + 4 * (tx >> 2);         // n0 offset; n1 = +4

    const float* Ag = A + (size_t)mTile * BM * I_DIM;
    const float* Bg = Bw + nTile * BN;

    unsigned long long acc2[4][TN];
#pragma unroll
    for (int i = 0; i < 4; i++)
#pragma unroll
        for (int j = 0; j < TN; j++) acc2[i][j] = 0ull;

    // preload tile 0
    {
        float4 a = *(const float4*)&Ag[(size_t)aRow * I_DIM + aCol];
        As[0][(aCol + 0) * BM + aRow] = a.x;
        As[0][(aCol + 1) * BM + aRow] = a.y;
        As[0][(aCol + 2) * BM + aRow] = a.z;
        As[0][(aCol + 3) * BM + aRow] = a.w;
        float4 b = *(const float4*)&Bg[(size_t)bRow * H_DIM + bCol];
        *(float4*)&Bs[0][bRow * BROW + bColP] = b;
    }
    __syncthreads();

#pragma unroll 1
    for (int it = 0; it < NKT; it++) {
        const int cur = it & 1;
        // prefetch next tile global -> regs
        float4 an, bn;
        if (it + 1 < NKT) {
            int k0 = (it + 1) * BK;
            an = *(const float4*)&Ag[(size_t)aRow * I_DIM + k0 + aCol];
            bn = *(const float4*)&Bg[(size_t)(k0 + bRow) * H_DIM + bCol];
        }

#pragma unroll
        for (int k = 0; k < BK; k++) {
            ulonglong2 am0 = *(const ulonglong2*)&As[cur][k * BM + ty * TM + 0];
            ulonglong2 am1 = *(const ulonglong2*)&As[cur][k * BM + ty * TM + 4];
            unsigned long long ap[4] = {am0.x, am0.y, am1.x, am1.y};
            float4 n0 = *(const float4*)&Bs[cur][k * BROW + nRdP + 0];
            float4 n1 = *(const float4*)&Bs[cur][k * BROW + nRdP + 4];
            unsigned long long bd[TN];
            bd[0] = pk2(n0.x, n0.x); bd[1] = pk2(n0.y, n0.y);
            bd[2] = pk2(n0.z, n0.z); bd[3] = pk2(n0.w, n0.w);
            bd[4] = pk2(n1.x, n1.x); bd[5] = pk2(n1.y, n1.y);
            bd[6] = pk2(n1.z, n1.z); bd[7] = pk2(n1.w, n1.w);
#pragma unroll
            for (int i = 0; i < 4; i++)
#pragma unroll
                for (int j = 0; j < TN; j++)
                    ffma2(acc2[i][j], ap[i], bd[j]);
        }

        if (it + 1 < NKT) {
            const int nxt = cur ^ 1;
            As[nxt][(aCol + 0) * BM + aRow] = an.x;
            As[nxt][(aCol + 1) * BM + aRow] = an.y;
            As[nxt][(aCol + 2) * BM + aRow] = an.z;
            As[nxt][(aCol + 3) * BM + aRow] = an.w;
            *(float4*)&Bs[nxt][bRow * BROW + bColP] = bn;
            __syncthreads();
        }
    }

    const int nBase = nTile * BN + tx * TN;
    float bv[TN];
#pragma unroll
    for (int j = 0; j < TN; j++) bv[j] = bias[nBase + j];

#pragma unroll
    for (int i = 0; i < 4; i++) {
        size_t row0 = (size_t)mTile * BM + ty * TM + 2 * i;
        float r0[TN], r1[TN];
#pragma unroll
        for (int j = 0; j < TN; j++) {
            float2 v = upk2(acc2[i][j]);
            r0[j] = v.x + bv[j];
            r1[j] = v.y + bv[j];
        }
        *(float4*)&g_X[row0 * H_DIM + nBase + 0] = make_float4(r0[0], r0[1], r0[2], r0[3]);
        *(float4*)&g_X[row0 * H_DIM + nBase + 4] = make_float4(r0[4], r0[5], r0[6], r0[7]);
        *(float4*)&g_X[(row0 + 1) * H_DIM + nBase + 0] = make_float4(r1[0], r1[1], r1[2], r1[3]);
        *(float4*)&g_X[(row0 + 1) * H_DIM + nBase + 4] = make_float4(r1[4], r1[5], r1[6], r1[7]);
    }
}

// ---------------------------------------------------------------------------
// Kernel 2: the recurrence (unchanged — measured 1083us).
// ---------------------------------------------------------------------------
#define SROW 272
#define BUF_F (2 * SROW)
#define PAIR_STRIDE_U32 36
#define SPLIT_STRIDE_U32 (128 * PAIR_STRIDE_U32 + 4)
#define SMEM_STATE_F (2 * BUF_F)
#define RNN_SMEM_F (SMEM_STATE_F + 4 * SPLIT_STRIDE_U32)
#define RNN_SMEM_B (RNN_SMEM_F * 4)

__global__ __launch_bounds__(512, 1) void rnn_kernel(
    const float* __restrict__ W,
    float* __restrict__ out,
    int write_state)
{
    extern __shared__ float sm[];
    float* S0 = sm;
    float* S1 = sm + BUF_F;
    uint32_t* WB = (uint32_t*)(sm + SMEM_STATE_F);

    const int tid = threadIdx.x;
    const int wid = tid >> 5;
    const int lane = tid & 31;
    const int p = wid * 8 + (lane & 7);
    const int s = lane >> 3;
    const int h0 = 2 * p;
    const int kbase = 64 * s;
    const int bidx0 = blockIdx.x * 2;
    const int hs = h0 + ((h0 >> 6) << 2);
    const bool sb0 = (s & 1);
    const int sb1 = (s >> 1);

    unsigned long long wrA[16], wrB[16];
#pragma unroll
    for (int j = 0; j < 16; j++) {
        int k = kbase + 2 * j;
        float2 wk  = *(const float2*)&W[(size_t)k * H_DIM + h0];
        float2 wk1 = *(const float2*)&W[(size_t)(k + 1) * H_DIM + h0];
        wrA[j] = pk2(wk.x, wk1.x);
        wrB[j] = pk2(wk.y, wk1.y);
    }

    uint32_t* myWB = WB + s * SPLIT_STRIDE_U32 + p * PAIR_STRIDE_U32;
#pragma unroll
    for (int j = 0; j < 16; j++) {
        int k = kbase + 32 + 2 * j;
        float2 wk  = *(const float2*)&W[(size_t)k * H_DIM + h0];
        float2 wk1 = *(const float2*)&W[(size_t)(k + 1) * H_DIM + h0];
        myWB[2 * j]     = f2bf2(wk.x, wk1.x);
        myWB[2 * j + 1] = f2bf2(wk.y, wk1.y);
    }

    for (int i = tid; i < SMEM_STATE_F; i += 512) sm[i] = 0.0f;
    __syncthreads();

    const uint4* wq = (const uint4*)myWB;
    const int stoff = sb1 * SROW + hs + (sb0 ? 1 : 0);
    const size_t goff = (size_t)(bidx0 + sb1) * H_DIM + h0 + (sb0 ? 1 : 0);
    float* outp = out + goff;
    const float* xp = g_X + goff;
    float* state_out = out + (size_t)T_DIM * B_DIM * H_DIM + goff;

    float x_nxt = *xp;

    auto step = [&](int t, const float* Sr, float* Sw) {
        const ulonglong2* su0 = (const ulonglong2*)(Sr + 68 * s);
        const ulonglong2* su1 = (const ulonglong2*)(Sr + SROW + 68 * s);

        float x_cur = x_nxt;
        int tn = (t + 1 < T_DIM) ? (t + 1) : t;
        x_nxt = xp[(size_t)tn * (B_DIM * H_DIM)];

        unsigned long long a00 = 0ull, a01 = 0ull, a10 = 0ull, a11 = 0ull;

#pragma unroll
        for (int j2 = 0; j2 < 8; j2++) {
            ulonglong2 s0 = su0[j2];
            ulonglong2 s1 = su1[j2];
            ffma2(a00, s0.x, wrA[2 * j2]);     ffma2(a01, s0.x, wrB[2 * j2]);
            ffma2(a00, s0.y, wrA[2 * j2 + 1]); ffma2(a01, s0.y, wrB[2 * j2 + 1]);
            ffma2(a10, s1.x, wrA[2 * j2]);     ffma2(a11, s1.x, wrB[2 * j2]);
            ffma2(a10, s1.y, wrA[2 * j2 + 1]); ffma2(a11, s1.y, wrB[2 * j2 + 1]);
        }
#pragma unroll
        for (int j2 = 0; j2 < 8; j2++) {
            uint4 q = wq[j2];
            unsigned long long wA0 = bf2f2(q.x);
            unsigned long long wB0 = bf2f2(q.y);
            unsigned long long wA1 = bf2f2(q.z);
            unsigned long long wB1 = bf2f2(q.w);
            ulonglong2 s0 = su0[8 + j2];
            ulonglong2 s1 = su1[8 + j2];
            ffma2(a00, s0.x, wA0); ffma2(a01, s0.x, wB0);
            ffma2(a00, s0.y, wA1); ffma2(a01, s0.y, wB1);
            ffma2(a10, s1.x, wA0); ffma2(a11, s1.x, wB0);
            ffma2(a10, s1.y, wA1); ffma2(a11, s1.y, wB1);
        }

        float f00 = hsum2(a00), f01 = hsum2(a01);
        float f10 = hsum2(a10), f11 = hsum2(a11);

        float m0 = sb0 ? f01 : f00;
        float m1 = sb0 ? f11 : f10;
        float o0 = sb0 ? f00 : f01;
        float o1 = sb0 ? f10 : f11;
        m0 += __shfl_xor_sync(0xffffffffu, o0, 8);
        m1 += __shfl_xor_sync(0xffffffffu, o1, 8);
        float mm = sb1 ? m1 : m0;
        float oo = sb1 ? m0 : m1;
        mm += __shfl_xor_sync(0xffffffffu, oo, 16);

        float h = fast_tanh(mm + x_cur);

        Sw[stoff] = h;
        outp[(size_t)t * (B_DIM * H_DIM)] = h;

        __syncthreads();
    };

#pragma unroll 1
    for (int t = 0; t < T_DIM; t += 2) {
        step(t,     S0, S1);
        step(t + 1, S1, S0);
    }

    if (write_state) *state_out = S0[stoff];
}

// ---------------------------------------------------------------------------
// Launch
// ---------------------------------------------------------------------------
extern "C" void kernel_launch(void* const* d_in, const int* in_sizes, int n_in,
                              void* d_out, int out_size)
{
    (void)n_in; (void)in_sizes;
    const float* inputs = (const float*)d_in[0];  // [T,B,I]
    const float* W_xh   = (const float*)d_in[1];  // [I,H]
    const float* W_hh   = (const float*)d_in[2];  // [H,H]
    const float* b_h    = (const float*)d_in[3];  // [H]
    float* out = (float*)d_out;

    const long long need = (long long)T_DIM * B_DIM * H_DIM + (long long)B_DIM * H_DIM;
    int write_state = ((long long)out_size >= need) ? 1 : 0;

    dim3 g1(M_DIM / BM, H_DIM / BN);
    gemm_xh_kernel<<<g1, 256>>>(inputs, W_xh, b_h);

    cudaFuncSetAttribute(rnn_kernel, cudaFuncAttributeMaxDynamicSharedMemorySize,
                         RNN_SMEM_B);
    rnn_kernel<<<B_DIM / 2, 512, RNN_SMEM_B>>>(W_hh, out, write_state);
}